// round 9
// baseline (speedup 1.0000x reference)
#include <cuda_runtime.h>
#include <cstdint>

#define M_SLOTS 10
#define HW      7744          // 88*88
#define HW4     1936          // HW in float4 units
#define ROWS    8192          // B*C
#define KC4     121           // chunk length in float4 units (1936/16)
#define NCH     16
#define RPB     16            // rows per block
#define NT      128           // 4 warps x 4 rows

typedef unsigned long long u64;

__device__ __forceinline__ u64 fma2(u64 a, u64 b, u64 c) {
    u64 d;
    asm("fma.rn.f32x2 %0, %1, %2, %3;" : "=l"(d) : "l"(a), "l"(b), "l"(c));
    return d;
}
__device__ __forceinline__ u64 pack2(float lo, float hi) {
    u64 t;
    asm("mov.b64 %0, {%1, %2};" : "=l"(t) : "f"(lo), "f"(hi));
    return t;
}
__device__ __forceinline__ void unpack2(u64 v, float& lo, float& hi) {
    asm("mov.b64 {%0, %1}, %2;" : "=f"(lo), "=f"(hi) : "l"(v));
}

__global__ __launch_bounds__(NT, 6)
void memaug_fused(const float* __restrict__ x,
                  const float* __restrict__ mem,
                  float* __restrict__ out) {
    __shared__ float4 w_s[M_SLOTS][KC4];   // 19,360 B chunk of mem
    __shared__ float  p_s[RPB][M_SLOTS];

    const int tid  = threadIdx.x;
    const int lane = tid & 31;
    const int warp = tid >> 5;
    const int row0 = blockIdx.x * RPB + warp * 4;

    const float4* __restrict__ m4 = (const float4*)mem;
    const float4* __restrict__ xr0 = (const float4*)(x + (size_t)(row0 + 0) * HW);
    const float4* __restrict__ xr1 = (const float4*)(x + (size_t)(row0 + 1) * HW);
    const float4* __restrict__ xr2 = (const float4*)(x + (size_t)(row0 + 2) * HW);
    const float4* __restrict__ xr3 = (const float4*)(x + (size_t)(row0 + 3) * HW);

    // ---------------- Phase 1: scores (scalar FFMA, 4 rows/warp) ----------
    float acc[4][M_SLOTS];
    #pragma unroll
    for (int r = 0; r < 4; r++)
        #pragma unroll
        for (int m = 0; m < M_SLOTS; m++) acc[r][m] = 0.0f;

    for (int c = 0; c < NCH; c++) {
        for (int idx = tid; idx < M_SLOTS * KC4; idx += NT) {
            int m = idx / KC4;
            int j = idx - m * KC4;
            w_s[m][j] = __ldg(&m4[(size_t)m * HW4 + c * KC4 + j]);
        }
        __syncthreads();

        const int base = c * KC4;
        for (int j = lane; j < KC4; j += 32) {
            float4 x0 = __ldcs(xr0 + base + j);
            float4 x1 = __ldcs(xr1 + base + j);
            float4 x2 = __ldcs(xr2 + base + j);
            float4 x3 = __ldcs(xr3 + base + j);
            #pragma unroll
            for (int m = 0; m < M_SLOTS; m++) {
                float4 w = w_s[m][j];
                acc[0][m] = fmaf(x0.x, w.x, fmaf(x0.y, w.y, fmaf(x0.z, w.z, fmaf(x0.w, w.w, acc[0][m]))));
                acc[1][m] = fmaf(x1.x, w.x, fmaf(x1.y, w.y, fmaf(x1.z, w.z, fmaf(x1.w, w.w, acc[1][m]))));
                acc[2][m] = fmaf(x2.x, w.x, fmaf(x2.y, w.y, fmaf(x2.z, w.z, fmaf(x2.w, w.w, acc[2][m]))));
                acc[3][m] = fmaf(x3.x, w.x, fmaf(x3.y, w.y, fmaf(x3.z, w.z, fmaf(x3.w, w.w, acc[3][m]))));
            }
        }
        __syncthreads();
    }

    // warp reduce -> p_s
    #pragma unroll
    for (int r = 0; r < 4; r++) {
        #pragma unroll
        for (int m = 0; m < M_SLOTS; m++) {
            float v = acc[r][m];
            v += __shfl_xor_sync(0xFFFFFFFFu, v, 16);
            v += __shfl_xor_sync(0xFFFFFFFFu, v, 8);
            v += __shfl_xor_sync(0xFFFFFFFFu, v, 4);
            v += __shfl_xor_sync(0xFFFFFFFFu, v, 2);
            v += __shfl_xor_sync(0xFFFFFFFFu, v, 1);
            if (lane == 0) p_s[warp * 4 + r][m] = v;
        }
    }
    __syncthreads();

    // softmax: one thread per row
    if (tid < RPB) {
        float s[M_SLOTS];
        float mx = -1e30f;
        #pragma unroll
        for (int m = 0; m < M_SLOTS; m++) { s[m] = p_s[tid][m]; mx = fmaxf(mx, s[m]); }
        float sum = 0.0f;
        #pragma unroll
        for (int m = 0; m < M_SLOTS; m++) { s[m] = __expf(s[m] - mx); sum += s[m]; }
        float inv = 1.0f / sum;
        #pragma unroll
        for (int m = 0; m < M_SLOTS; m++) p_s[tid][m] = s[m] * inv;
    }
    __syncthreads();

    // ---------------- Phase 2: value, row-pair packed f32x2 ---------------
    // p01[m] = (p[row0+0][m], p[row0+1][m]),  p23[m] = (p[row0+2][m], p[row0+3][m])
    u64 p01[M_SLOTS], p23[M_SLOTS];
    #pragma unroll
    for (int m = 0; m < M_SLOTS; m++) {
        p01[m] = pack2(p_s[warp * 4 + 0][m], p_s[warp * 4 + 1][m]);
        p23[m] = pack2(p_s[warp * 4 + 2][m], p_s[warp * 4 + 3][m]);
    }

    float4* __restrict__ o0 = (float4*)(out + (size_t)(row0 + 0) * HW);
    float4* __restrict__ o1 = (float4*)(out + (size_t)(row0 + 1) * HW);
    float4* __restrict__ o2 = (float4*)(out + (size_t)(row0 + 2) * HW);
    float4* __restrict__ o3 = (float4*)(out + (size_t)(row0 + 3) * HW);

    for (int c = 0; c < NCH; c++) {
        for (int idx = tid; idx < M_SLOTS * KC4; idx += NT) {
            int m = idx / KC4;
            int j = idx - m * KC4;
            w_s[m][j] = __ldg(&m4[(size_t)m * HW4 + c * KC4 + j]);
        }
        __syncthreads();

        const int base = c * KC4;
        for (int j = lane; j < KC4; j += 32) {
            // accumulators hold (row0, row1) and (row2, row3) pairs per component
            u64 a01x = 0ull, a01y = 0ull, a01z = 0ull, a01w = 0ull;
            u64 a23x = 0ull, a23y = 0ull, a23z = 0ull, a23w = 0ull;
            #pragma unroll
            for (int m = 0; m < M_SLOTS; m++) {
                float4 w = w_s[m][j];
                u64 wx = pack2(w.x, w.x);
                u64 wy = pack2(w.y, w.y);
                u64 wz = pack2(w.z, w.z);
                u64 ww = pack2(w.w, w.w);
                a01x = fma2(p01[m], wx, a01x);  a23x = fma2(p23[m], wx, a23x);
                a01y = fma2(p01[m], wy, a01y);  a23y = fma2(p23[m], wy, a23y);
                a01z = fma2(p01[m], wz, a01z);  a23z = fma2(p23[m], wz, a23z);
                a01w = fma2(p01[m], ww, a01w);  a23w = fma2(p23[m], ww, a23w);
            }
            float4 v0, v1, v2, v3;
            unpack2(a01x, v0.x, v1.x);  unpack2(a01y, v0.y, v1.y);
            unpack2(a01z, v0.z, v1.z);  unpack2(a01w, v0.w, v1.w);
            unpack2(a23x, v2.x, v3.x);  unpack2(a23y, v2.y, v3.y);
            unpack2(a23z, v2.z, v3.z);  unpack2(a23w, v2.w, v3.w);
            __stcs(o0 + base + j, v0);
            __stcs(o1 + base + j, v1);
            __stcs(o2 + base + j, v2);
            __stcs(o3 + base + j, v3);
        }
        __syncthreads();
    }
}

extern "C" void kernel_launch(void* const* d_in, const int* in_sizes, int n_in,
                              void* d_out, int out_size) {
    const float* x   = (const float*)d_in[0];   // [32,256,88,88]
    const float* mem = (const float*)d_in[1];   // [10,88,88]
    float* out = (float*)d_out;

    dim3 grid(ROWS / RPB);    // 512 blocks
    memaug_fused<<<grid, NT>>>(x, mem, out);
}